// round 16
// baseline (speedup 1.0000x reference)
#include <cuda_runtime.h>
#include <cuda_fp16.h>

// Deform_Conv_V1: fused offset-conv + deformable conv + ReLU.
// B=8, Cin=32, H=W=160, Cout=32, K=3, PAD=1.
// Inputs: x (8,32,160,160), w_off (18,32,3,3), b_off (18,), w_dcn (32,32,3,3)
// Output: (8,32,160,160) fp32.
//
// R16: R15 two-kernel split; kernel B's weight reads split across ports WITHOUT
//      smem: o0-15 via __constant__ (LDC), o16-31 via warp-uniform LDG.128 from
//      a __device__ table (L1D-cached broadcast, no carveout). Halves B's
//      constant-port serialization (the R15 binder).

#define Hn  160
#define Wn  160
#define CIN 32
#define COUT 32
#define HWs (Hn * Wn)
#define NPIX (8 * HWs)

#define WOFF_T_ELEMS  (9 * 32 * 20)   // [k][c][oc pad 20] = 5760
#define WDCNL_T_ELEMS (9 * 32 * 16)   // [k][c][o 0..15]   = 4608
#define WDCNH_T_ELEMS (9 * 32 * 16)   // [k][c][o 16..31]  = 4608

__constant__ float c_woff[WOFF_T_ELEMS];      // 22.5 KB
__constant__ float c_wdcn_lo[WDCNL_T_ELEMS];  // 18 KB
__device__ float g_stage[WOFF_T_ELEMS + WDCNL_T_ELEMS];
__device__ __align__(16) float g_wdcn_hi[WDCNH_T_ELEMS];   // LDG table, L1-cached
__device__ unsigned int g_offs[9 * NPIX];     // half2(dy,dx), 7.4 MB

typedef unsigned long long u64;

__device__ __forceinline__ u64 pack2(float a, float b) {
    u64 r; asm("mov.b64 %0, {%1, %2};" : "=l"(r) : "f"(a), "f"(b)); return r;
}
__device__ __forceinline__ void unpack2(u64 v, float& a, float& b) {
    asm("mov.b64 {%0, %1}, %2;" : "=f"(a), "=f"(b) : "l"(v));
}
__device__ __forceinline__ void ffma2(u64& d, u64 a, u64 b) {
    asm("fma.rn.f32x2 %0, %1, %2, %0;" : "+l"(d) : "l"(a), "l"(b));
}

__global__ void prep_kernel(const float* __restrict__ w_off,
                            const float* __restrict__ w_dcn)
{
    const int i = blockIdx.x * 256 + threadIdx.x;
    if (i < WOFF_T_ELEMS) {   // [k][c][oc pad 20]
        int k = i / 640;
        int r = i - k * 640;
        int c = r / 20;
        int oc = r - c * 20;
        g_stage[i] = (oc < 18) ? w_off[oc * 288 + c * 9 + k] : 0.0f;
    }
    if (i < WDCNL_T_ELEMS) {  // lo: [k][c][o 0..15] -> staged for constant copy
        int k = i / 512;
        int r = i - k * 512;
        int c = r >> 4;
        int o = r & 15;
        g_stage[WOFF_T_ELEMS + i] = w_dcn[o * 288 + c * 9 + k];
    }
    if (i < WDCNH_T_ELEMS) {  // hi: [k][c][o 16..31] -> direct device table
        int k = i / 512;
        int r = i - k * 512;
        int c = r >> 4;
        int o = (r & 15) + 16;
        g_wdcn_hi[i] = w_dcn[o * 288 + c * 9 + k];
    }
}

// ================= Kernel A: offset conv, 4 px/thread =================
__global__ __launch_bounds__(128, 4)
void offs_kernel(const float* __restrict__ x,
                 const float* __restrict__ b_off)
{
    const int tid = threadIdx.x;
    const int P0 = blockIdx.x * 512;
    const int b  = P0 / HWs;
    const int hwBase = P0 - b * HWs;
    const float* xb = x + (size_t)b * CIN * HWs;

    int hw[4], hh[4], wwp[4];
#pragma unroll
    for (int p = 0; p < 4; p++) {
        hw[p]  = hwBase + tid + 128 * p;
        hh[p]  = hw[p] / Wn;
        wwp[p] = hw[p] - hh[p] * Wn;
    }

    u64 o2[4][9];
#pragma unroll
    for (int t = 0; t < 9; t++) {
        u64 bv = pack2(__ldg(&b_off[2 * t]), __ldg(&b_off[2 * t + 1]));
#pragma unroll
        for (int p = 0; p < 4; p++) o2[p][t] = bv;
    }

#pragma unroll
    for (int k = 0; k < 9; k++) {
        const int ky = k / 3, kx = k - 3 * (k / 3);
        int idx[4]; bool v[4];
#pragma unroll
        for (int p = 0; p < 4; p++) {
            int yy = hh[p] - 1 + ky;
            int xx = wwp[p] - 1 + kx;
            v[p] = (yy >= 0) && (yy < Hn) && (xx >= 0) && (xx < Wn);
            idx[p] = min(max(yy, 0), Hn - 1) * Wn + min(max(xx, 0), Wn - 1);
        }
#pragma unroll 4
        for (int c = 0; c < CIN; c++) {
            const float* xc = xb + c * HWs;
            u64 s[4];
#pragma unroll
            for (int p = 0; p < 4; p++) {
                float xv = v[p] ? __ldg(xc + idx[p]) : 0.0f;
                s[p] = pack2(xv, xv);
            }
            const ulonglong2* wc = (const ulonglong2*)(c_woff + k * 640 + c * 20);
#pragma unroll
            for (int j = 0; j < 4; j++) {
                ulonglong2 q = wc[j];
#pragma unroll
                for (int p = 0; p < 4; p++) {
                    ffma2(o2[p][2 * j],     s[p], q.x);
                    ffma2(o2[p][2 * j + 1], s[p], q.y);
                }
            }
            ulonglong2 q4 = wc[4];
#pragma unroll
            for (int p = 0; p < 4; p++) ffma2(o2[p][8], s[p], q4.x);
        }
    }

    const int pixBase = P0 + tid;
#pragma unroll
    for (int t = 0; t < 9; t++) {
#pragma unroll
        for (int p = 0; p < 4; p++) {
            float dy, dx; unpack2(o2[p][t], dy, dx);
            __half2 h2 = __floats2half2_rn(dy, dx);
            g_offs[t * NPIX + pixBase + 128 * p] = *(unsigned int*)&h2;
        }
    }
}

// ================= Kernel B: deformable conv, 2 px/thread =================
__global__ __launch_bounds__(128, 4)
void dcn_kernel(const float* __restrict__ x,
                float* __restrict__ out)
{
    const int tid = threadIdx.x;
    const int P0 = blockIdx.x * 256;
    const int b  = P0 / HWs;
    const int hw0 = P0 - b * HWs;
    const int hwA = hw0 + tid;
    const int hwB = hwA + 128;
    const int hA = hwA / Wn, wA = hwA - hA * Wn;
    const int hB = hwB / Wn, wB = hwB - hB * Wn;
    const int pixA = P0 + tid;
    const float* xb = x + (size_t)b * CIN * HWs;

    u64 acca[16], accb[16];
#pragma unroll
    for (int m = 0; m < 16; m++) { acca[m] = 0ULL; accb[m] = 0ULL; }

#pragma unroll
    for (int k = 0; k < 9; k++) {
        const int ky = k / 3, kx = k - 3 * (k / 3);

        float aw00, aw01, aw10, aw11; int aI, aDx, aDy;
        {
            unsigned int hb = __ldg(&g_offs[k * NPIX + pixA]);
            float2 d = __half22float2(*(__half2*)&hb);
            const float py = (float)(hA - 1 + ky) + d.x;
            const float px = (float)(wA - 1 + kx) + d.y;
            const float y0f = floorf(py), x0f = floorf(px);
            const float wy1 = py - y0f, wx1 = px - x0f;
            const float wy0 = 1.0f - wy1, wx0 = 1.0f - wx1;
            const float y1f = y0f + 1.0f, x1f = x0f + 1.0f;
            const bool vy0 = (y0f >= 0.0f) && (y0f <= (float)(Hn - 1));
            const bool vy1 = (y1f >= 0.0f) && (y1f <= (float)(Hn - 1));
            const bool vx0 = (x0f >= 0.0f) && (x0f <= (float)(Wn - 1));
            const bool vx1 = (x1f >= 0.0f) && (x1f <= (float)(Wn - 1));
            aw00 = (vy0 && vx0) ? wy0 * wx0 : 0.0f;
            aw01 = (vy0 && vx1) ? wy0 * wx1 : 0.0f;
            aw10 = (vy1 && vx0) ? wy1 * wx0 : 0.0f;
            aw11 = (vy1 && vx1) ? wy1 * wx1 : 0.0f;
            const int iy0 = min(max((int)y0f, 0), Hn - 1);
            const int iy1 = min(max((int)y1f, 0), Hn - 1);
            const int ix0 = min(max((int)x0f, 0), Wn - 1);
            const int ix1 = min(max((int)x1f, 0), Wn - 1);
            aI  = iy0 * Wn + ix0;
            aDx = ix1 - ix0;
            aDy = (iy1 - iy0) * Wn;
        }
        float bw00, bw01, bw10, bw11; int bI, bDx, bDy;
        {
            unsigned int hb = __ldg(&g_offs[k * NPIX + pixA + 128]);
            float2 d = __half22float2(*(__half2*)&hb);
            const float py = (float)(hB - 1 + ky) + d.x;
            const float px = (float)(wB - 1 + kx) + d.y;
            const float y0f = floorf(py), x0f = floorf(px);
            const float wy1 = py - y0f, wx1 = px - x0f;
            const float wy0 = 1.0f - wy1, wx0 = 1.0f - wx1;
            const float y1f = y0f + 1.0f, x1f = x0f + 1.0f;
            const bool vy0 = (y0f >= 0.0f) && (y0f <= (float)(Hn - 1));
            const bool vy1 = (y1f >= 0.0f) && (y1f <= (float)(Hn - 1));
            const bool vx0 = (x0f >= 0.0f) && (x0f <= (float)(Wn - 1));
            const bool vx1 = (x1f >= 0.0f) && (x1f <= (float)(Wn - 1));
            bw00 = (vy0 && vx0) ? wy0 * wx0 : 0.0f;
            bw01 = (vy0 && vx1) ? wy0 * wx1 : 0.0f;
            bw10 = (vy1 && vx0) ? wy1 * wx0 : 0.0f;
            bw11 = (vy1 && vx1) ? wy1 * wx1 : 0.0f;
            const int iy0 = min(max((int)y0f, 0), Hn - 1);
            const int iy1 = min(max((int)y1f, 0), Hn - 1);
            const int ix0 = min(max((int)x0f, 0), Wn - 1);
            const int ix1 = min(max((int)x1f, 0), Wn - 1);
            bI  = iy0 * Wn + ix0;
            bDx = ix1 - ix0;
            bDy = (iy1 - iy0) * Wn;
        }

        const u64 W00 = pack2(aw00, bw00);
        const u64 W01 = pack2(aw01, bw01);
        const u64 W10 = pack2(aw10, bw10);
        const u64 W11 = pack2(aw11, bw11);

#pragma unroll 4
        for (int c = 0; c < CIN; c++) {
            const float* xc = xb + c * HWs;
            const float* ga = xc + aI;
            const float* gb = xc + bI;
            const u64 P00 = pack2(__ldg(ga),             __ldg(gb));
            const u64 P01 = pack2(__ldg(ga + aDx),       __ldg(gb + bDx));
            const u64 P10 = pack2(__ldg(ga + aDy),       __ldg(gb + bDy));
            const u64 P11 = pack2(__ldg(ga + aDy + aDx), __ldg(gb + bDy + bDx));
            u64 vab = 0ULL;
            ffma2(vab, W00, P00);
            ffma2(vab, W01, P01);
            ffma2(vab, W10, P10);
            ffma2(vab, W11, P11);
            float va, vb; unpack2(vab, va, vb);
            const u64 va2 = pack2(va, va);
            const u64 vb2 = pack2(vb, vb);

            // o 0..15 via constant port (4 x LDC.128)
            const ulonglong2* wlo = (const ulonglong2*)(c_wdcn_lo + k * 512 + c * 16);
#pragma unroll
            for (int j = 0; j < 4; j++) {
                ulonglong2 q = wlo[j];
                ffma2(acca[2 * j],     va2, q.x);
                ffma2(acca[2 * j + 1], va2, q.y);
                ffma2(accb[2 * j],     vb2, q.x);
                ffma2(accb[2 * j + 1], vb2, q.y);
            }
            // o 16..31 via warp-uniform LDG.128 (L1D-cached broadcast)
            const ulonglong2* whi = (const ulonglong2*)(g_wdcn_hi + k * 512 + c * 16);
#pragma unroll
            for (int j = 0; j < 4; j++) {
                ulonglong2 q = __ldg(whi + j);
                ffma2(acca[8 + 2 * j],     va2, q.x);
                ffma2(acca[8 + 2 * j + 1], va2, q.y);
                ffma2(accb[8 + 2 * j],     vb2, q.x);
                ffma2(accb[8 + 2 * j + 1], vb2, q.y);
            }
        }
    }

    float* ob = out + (size_t)b * COUT * HWs;
#pragma unroll
    for (int m = 0; m < 16; m++) {
        float a0, a1, c0, c1;
        unpack2(acca[m], a0, a1);
        unpack2(accb[m], c0, c1);
        ob[(2 * m)     * HWs + hwA] = fmaxf(a0, 0.0f);
        ob[(2 * m + 1) * HWs + hwA] = fmaxf(a1, 0.0f);
        ob[(2 * m)     * HWs + hwB] = fmaxf(c0, 0.0f);
        ob[(2 * m + 1) * HWs + hwB] = fmaxf(c1, 0.0f);
    }
}

extern "C" void kernel_launch(void* const* d_in, const int* in_sizes, int n_in,
                              void* d_out, int out_size)
{
    const float* x     = (const float*)d_in[0];
    const float* w_off = (const float*)d_in[1];
    const float* b_off = (const float*)d_in[2];
    const float* w_dcn = (const float*)d_in[3];
    float* out = (float*)d_out;

    void* stage_dev = nullptr;
    cudaGetSymbolAddress(&stage_dev, g_stage);

    prep_kernel<<<(WOFF_T_ELEMS + 255) / 256, 256>>>(w_off, w_dcn);
    cudaMemcpyToSymbolAsync(c_woff, stage_dev,
                            WOFF_T_ELEMS * sizeof(float), 0,
                            cudaMemcpyDeviceToDevice, 0);
    cudaMemcpyToSymbolAsync(c_wdcn_lo, (const char*)stage_dev + WOFF_T_ELEMS * sizeof(float),
                            WDCNL_T_ELEMS * sizeof(float), 0,
                            cudaMemcpyDeviceToDevice, 0);

    offs_kernel<<<NPIX / 512, 128>>>(x, b_off);     // 400 CTAs
    dcn_kernel<<<NPIX / 256, 128>>>(x, out);        // 800 CTAs
}

// round 17
// speedup vs baseline: 1.2454x; 1.2454x over previous
#include <cuda_runtime.h>
#include <cuda_fp16.h>

// Deform_Conv_V1: fused offset-conv + deformable conv + ReLU.
// B=8, Cin=32, H=W=160, Cout=32, K=3, PAD=1.
// Inputs: x (8,32,160,160), w_off (18,32,3,3), b_off (18,), w_dcn (32,32,3,3)
// Output: (8,32,160,160) fp32.
//
// R17: kernel B restructured as per-tap sample->smem->register-tiled GEMM.
//      Each weight LDC.128 now feeds an 8-pixel tile (was 2), cutting the
//      constant-port serialization ~4x. Sampled pixel pairs come out of smem
//      pre-packed for FFMA2. Kernel A (offset conv) unchanged from R15.

#define Hn  160
#define Wn  160
#define CIN 32
#define COUT 32
#define HWs (Hn * Wn)
#define NPIX (8 * HWs)

#define WDCN_T_ELEMS (9 * 32 * 32)   // [k][c][o]         = 9216
#define WOFF_T_ELEMS (9 * 32 * 20)   // [k][c][oc pad 20] = 5760

__constant__ float c_wdcn[WDCN_T_ELEMS];   // 36 KB
__constant__ float c_woff[WOFF_T_ELEMS];   // 22.5 KB
__device__ float g_stage[WDCN_T_ELEMS + WOFF_T_ELEMS];
__device__ unsigned int g_offs[9 * NPIX];  // half2(dy,dx), 7.4 MB

typedef unsigned long long u64;

__device__ __forceinline__ u64 pack2(float a, float b) {
    u64 r; asm("mov.b64 %0, {%1, %2};" : "=l"(r) : "f"(a), "f"(b)); return r;
}
__device__ __forceinline__ void unpack2(u64 v, float& a, float& b) {
    asm("mov.b64 {%0, %1}, %2;" : "=f"(a), "=f"(b) : "l"(v));
}
__device__ __forceinline__ void ffma2(u64& d, u64 a, u64 b) {
    asm("fma.rn.f32x2 %0, %1, %2, %0;" : "+l"(d) : "l"(a), "l"(b));
}

__global__ void prep_kernel(const float* __restrict__ w_off,
                            const float* __restrict__ w_dcn)
{
    const int i = blockIdx.x * 256 + threadIdx.x;
    if (i < WDCN_T_ELEMS) {   // [k][c][o]
        int k = i >> 10;
        int r = i & 1023;
        int c = r >> 5;
        int o = r & 31;
        g_stage[i] = w_dcn[o * 288 + c * 9 + k];
    }
    if (i < WOFF_T_ELEMS) {   // [k][c][oc pad 20]
        int k = i / 640;
        int r = i - k * 640;
        int c = r / 20;
        int oc = r - c * 20;
        g_stage[WDCN_T_ELEMS + i] = (oc < 18) ? w_off[oc * 288 + c * 9 + k] : 0.0f;
    }
}

// ================= Kernel A: offset conv, 4 px/thread (unchanged) =================
__global__ __launch_bounds__(128, 4)
void offs_kernel(const float* __restrict__ x,
                 const float* __restrict__ b_off)
{
    const int tid = threadIdx.x;
    const int P0 = blockIdx.x * 512;
    const int b  = P0 / HWs;
    const int hwBase = P0 - b * HWs;
    const float* xb = x + (size_t)b * CIN * HWs;

    int hw[4], hh[4], wwp[4];
#pragma unroll
    for (int p = 0; p < 4; p++) {
        hw[p]  = hwBase + tid + 128 * p;
        hh[p]  = hw[p] / Wn;
        wwp[p] = hw[p] - hh[p] * Wn;
    }

    u64 o2[4][9];
#pragma unroll
    for (int t = 0; t < 9; t++) {
        u64 bv = pack2(__ldg(&b_off[2 * t]), __ldg(&b_off[2 * t + 1]));
#pragma unroll
        for (int p = 0; p < 4; p++) o2[p][t] = bv;
    }

#pragma unroll
    for (int k = 0; k < 9; k++) {
        const int ky = k / 3, kx = k - 3 * (k / 3);
        int idx[4]; bool v[4];
#pragma unroll
        for (int p = 0; p < 4; p++) {
            int yy = hh[p] - 1 + ky;
            int xx = wwp[p] - 1 + kx;
            v[p] = (yy >= 0) && (yy < Hn) && (xx >= 0) && (xx < Wn);
            idx[p] = min(max(yy, 0), Hn - 1) * Wn + min(max(xx, 0), Wn - 1);
        }
#pragma unroll 4
        for (int c = 0; c < CIN; c++) {
            const float* xc = xb + c * HWs;
            u64 s[4];
#pragma unroll
            for (int p = 0; p < 4; p++) {
                float xv = v[p] ? __ldg(xc + idx[p]) : 0.0f;
                s[p] = pack2(xv, xv);
            }
            const ulonglong2* wc = (const ulonglong2*)(c_woff + k * 640 + c * 20);
#pragma unroll
            for (int j = 0; j < 4; j++) {
                ulonglong2 q = wc[j];
#pragma unroll
                for (int p = 0; p < 4; p++) {
                    ffma2(o2[p][2 * j],     s[p], q.x);
                    ffma2(o2[p][2 * j + 1], s[p], q.y);
                }
            }
            ulonglong2 q4 = wc[4];
#pragma unroll
            for (int p = 0; p < 4; p++) ffma2(o2[p][8], s[p], q4.x);
        }
    }

    const int pixBase = P0 + tid;
#pragma unroll
    for (int t = 0; t < 9; t++) {
#pragma unroll
        for (int p = 0; p < 4; p++) {
            float dy, dx; unpack2(o2[p][t], dy, dx);
            __half2 h2 = __floats2half2_rn(dy, dx);
            g_offs[t * NPIX + pixBase + 128 * p] = *(unsigned int*)&h2;
        }
    }
}

// ================= Kernel B: sample -> smem -> tiled GEMM =================
// CTA = 128 threads = 128 pixels. Thread (pixTile = tid&15, oTile = tid>>4)
// accumulates an 8-pixel x 4-output tile.
__global__ __launch_bounds__(128, 4)
void dcn_kernel(const float* __restrict__ x,
                float* __restrict__ out)
{
    __shared__ float vals[32][128];   // [c][pixel-in-CTA], 16 KB

    const int tid = threadIdx.x;
    const int P0 = blockIdx.x * 128;           // 25600 % 128 == 0: no b straddle
    const int b  = P0 / HWs;
    const int hw0 = P0 - b * HWs;
    const int hwP = hw0 + tid;
    const int hP = hwP / Wn, wP = hwP - hP * Wn;
    const int pix = P0 + tid;
    const float* xb = x + (size_t)b * CIN * HWs;

    const int pixTile = tid & 15;              // 0..15 -> pixels [8*pt, 8*pt+8)
    const int oTile   = tid >> 4;              // 0..7  -> outputs [4*ot, 4*ot+4)

    u64 acc[16];                               // acc[j*4+q] = (px 2q, px 2q+1) for output j
#pragma unroll
    for (int m = 0; m < 16; m++) acc[m] = 0ULL;

#pragma unroll 1
    for (int k = 0; k < 9; k++) {
        const int ky = k / 3, kx = k - 3 * (k / 3);

        // ---- Phase 1: each thread samples its own pixel, all 32 channels ----
        {
            unsigned int hb = __ldg(&g_offs[k * NPIX + pix]);
            float2 d = __half22float2(*(__half2*)&hb);
            const float py = (float)(hP - 1 + ky) + d.x;
            const float px = (float)(wP - 1 + kx) + d.y;
            const float y0f = floorf(py), x0f = floorf(px);
            const float wy1 = py - y0f, wx1 = px - x0f;
            const float wy0 = 1.0f - wy1, wx0 = 1.0f - wx1;
            const float y1f = y0f + 1.0f, x1f = x0f + 1.0f;
            const bool vy0 = (y0f >= 0.0f) && (y0f <= (float)(Hn - 1));
            const bool vy1 = (y1f >= 0.0f) && (y1f <= (float)(Hn - 1));
            const bool vx0 = (x0f >= 0.0f) && (x0f <= (float)(Wn - 1));
            const bool vx1 = (x1f >= 0.0f) && (x1f <= (float)(Wn - 1));
            const float w00 = (vy0 && vx0) ? wy0 * wx0 : 0.0f;
            const float w01 = (vy0 && vx1) ? wy0 * wx1 : 0.0f;
            const float w10 = (vy1 && vx0) ? wy1 * wx0 : 0.0f;
            const float w11 = (vy1 && vx1) ? wy1 * wx1 : 0.0f;
            const int iy0 = min(max((int)y0f, 0), Hn - 1);
            const int iy1 = min(max((int)y1f, 0), Hn - 1);
            const int ix0 = min(max((int)x0f, 0), Wn - 1);
            const int ix1 = min(max((int)x1f, 0), Wn - 1);
            const int i00 = iy0 * Wn + ix0;
            const int dX  = ix1 - ix0;
            const int dY  = (iy1 - iy0) * Wn;
#pragma unroll 4
            for (int c = 0; c < CIN; c++) {
                const float* gp = xb + c * HWs + i00;
                const float val = fmaf(w00, __ldg(gp),
                                  fmaf(w01, __ldg(gp + dX),
                                  fmaf(w10, __ldg(gp + dY),
                                       w11 * __ldg(gp + dY + dX))));
                vals[c][tid] = val;
            }
        }
        __syncthreads();

        // ---- Phase 2: tiled GEMM: 8 px x 4 out per thread ----
        const float4* wk = (const float4*)(c_wdcn + k * 1024);   // [c][8 float4]
#pragma unroll 4
        for (int c = 0; c < CIN; c++) {
            const ulonglong2* vp = (const ulonglong2*)(&vals[c][pixTile * 8]);
            const ulonglong2 vA = vp[0];       // (px0,px1),(px2,px3) packed
            const ulonglong2 vB = vp[1];       // (px4,px5),(px6,px7) packed
            const float4 wq = wk[c * 8 + oTile];
            const u64 w0 = pack2(wq.x, wq.x);
            const u64 w1 = pack2(wq.y, wq.y);
            const u64 w2 = pack2(wq.z, wq.z);
            const u64 w3 = pack2(wq.w, wq.w);
            ffma2(acc[0],  vA.x, w0); ffma2(acc[1],  vA.y, w0);
            ffma2(acc[2],  vB.x, w0); ffma2(acc[3],  vB.y, w0);
            ffma2(acc[4],  vA.x, w1); ffma2(acc[5],  vA.y, w1);
            ffma2(acc[6],  vB.x, w1); ffma2(acc[7],  vB.y, w1);
            ffma2(acc[8],  vA.x, w2); ffma2(acc[9],  vA.y, w2);
            ffma2(acc[10], vB.x, w2); ffma2(acc[11], vB.y, w2);
            ffma2(acc[12], vA.x, w3); ffma2(acc[13], vA.y, w3);
            ffma2(acc[14], vB.x, w3); ffma2(acc[15], vB.y, w3);
        }
        __syncthreads();   // vals reused next tap
    }

    // ---- Epilogue: ReLU + float2 stores (8 px x 4 out per thread) ----
    float* ob = out + (size_t)b * COUT * HWs + hw0 + pixTile * 8;
#pragma unroll
    for (int j = 0; j < 4; j++) {
        float* orow = ob + (oTile * 4 + j) * HWs;
#pragma unroll
        for (int q = 0; q < 4; q++) {
            float a0, a1;
            unpack2(acc[j * 4 + q], a0, a1);
            float2 r;
            r.x = fmaxf(a0, 0.0f);
            r.y = fmaxf(a1, 0.0f);
            *(float2*)(orow + 2 * q) = r;
        }
    }
}

extern "C" void kernel_launch(void* const* d_in, const int* in_sizes, int n_in,
                              void* d_out, int out_size)
{
    const float* x     = (const float*)d_in[0];
    const float* w_off = (const float*)d_in[1];
    const float* b_off = (const float*)d_in[2];
    const float* w_dcn = (const float*)d_in[3];
    float* out = (float*)d_out;

    void* stage_dev = nullptr;
    cudaGetSymbolAddress(&stage_dev, g_stage);

    prep_kernel<<<(WDCN_T_ELEMS + 255) / 256, 256>>>(w_off, w_dcn);
    cudaMemcpyToSymbolAsync(c_wdcn, stage_dev,
                            WDCN_T_ELEMS * sizeof(float), 0,
                            cudaMemcpyDeviceToDevice, 0);
    cudaMemcpyToSymbolAsync(c_woff, (const char*)stage_dev + WDCN_T_ELEMS * sizeof(float),
                            WOFF_T_ELEMS * sizeof(float), 0,
                            cudaMemcpyDeviceToDevice, 0);

    offs_kernel<<<NPIX / 512, 128>>>(x, b_off);     // 400 CTAs
    dcn_kernel<<<NPIX / 128, 128>>>(x, out);        // 1600 CTAs
}